// round 3
// baseline (speedup 1.0000x reference)
#include <cuda_runtime.h>
#include <cuda_bf16.h>
#include <math.h>

// Problem constants
#define B_ 4
#define M_ 2048
#define IN_DIM_ 512
#define D_ 1024
#define H_ 4
#define NL_ 2
#define HD_ 256
#define HD2_ 128
#define FF_ 4096
#define ROWS_ (B_ * M_)          // 8192
#define SCALE_ 0.0625f           // 1/sqrt(256)

// ---------------- scratch (device globals; no allocations allowed) ----------
__device__ float g_h[(size_t)ROWS_ * D_];             // residual stream  (32MB)
__device__ float g_y[(size_t)ROWS_ * D_];             // LN output        (32MB)
__device__ float g_qkv[(size_t)ROWS_ * 3 * D_];       // qkv projection   (96MB)
__device__ float g_scores[(size_t)B_ * H_ * M_ * M_]; // attn scores      (256MB)
__device__ float g_attn[(size_t)ROWS_ * D_];          // attn output      (32MB)
__device__ float g_ffn[(size_t)ROWS_ * FF_];          // ffn hidden       (128MB)
__device__ float g_cos[(size_t)ROWS_ * HD2_];         // rope cos         (4MB)
__device__ float g_sin[(size_t)ROWS_ * HD2_];         // rope sin         (4MB)

// ---------------- reductions ------------------------------------------------
__device__ __forceinline__ float blockReduceSum(float v) {
    __shared__ float sh[32];
    int lane = threadIdx.x & 31, w = threadIdx.x >> 5;
    __syncthreads();
    #pragma unroll
    for (int o = 16; o; o >>= 1) v += __shfl_down_sync(0xffffffffu, v, o);
    if (!lane) sh[w] = v;
    __syncthreads();
    v = (threadIdx.x < (blockDim.x >> 5)) ? sh[threadIdx.x] : 0.f;
    if (w == 0) {
        #pragma unroll
        for (int o = 16; o; o >>= 1) v += __shfl_down_sync(0xffffffffu, v, o);
        if (!lane) sh[0] = v;
    }
    __syncthreads();
    return sh[0];
}

__device__ __forceinline__ float blockReduceMax(float v) {
    __shared__ float sh[32];
    int lane = threadIdx.x & 31, w = threadIdx.x >> 5;
    __syncthreads();
    #pragma unroll
    for (int o = 16; o; o >>= 1) v = fmaxf(v, __shfl_down_sync(0xffffffffu, v, o));
    if (!lane) sh[w] = v;
    __syncthreads();
    v = (threadIdx.x < (blockDim.x >> 5)) ? sh[threadIdx.x] : -INFINITY;
    if (w == 0) {
        #pragma unroll
        for (int o = 16; o; o >>= 1) v = fmaxf(v, __shfl_down_sync(0xffffffffu, v, o));
        if (!lane) sh[0] = v;
    }
    __syncthreads();
    return sh[0];
}

// ---------------- GEMM: C[M,N] = A[M,K] @ B (optionally B^T) ----------------
// Double-buffered smem pipeline.
// EPI: 0 = store, 1 = +bias store, 2 = +bias, gelu, store, 3 = C += val, 4 = C += val + bias
#define BM 128
#define BN 128
#define BK 8
#define TM 8
#define TN 8

template <int EPI, int TRANSB>
__global__ __launch_bounds__(256) void gemm_k(
    const float* __restrict__ A, const float* __restrict__ Bm,
    const float* __restrict__ bias, float* __restrict__ C,
    int K, int lda, int ldb, int ldc, int Hdim,
    long sA_b, long sA_h, long sB_b, long sB_h, long sC_b, long sC_h)
{
    __shared__ float As[2][BK][BM];
    __shared__ float Bs[2][BK][BN];

    int zb = blockIdx.z / Hdim;
    int zh = blockIdx.z % Hdim;
    A  += (long)zb * sA_b + (long)zh * sA_h;
    Bm += (long)zb * sB_b + (long)zh * sB_h;
    C  += (long)zb * sC_b + (long)zh * sC_h;

    int bm = blockIdx.y * BM;
    int bn = blockIdx.x * BN;
    int tid = threadIdx.x;

    float acc[TM][TN];
    #pragma unroll
    for (int i = 0; i < TM; i++)
        #pragma unroll
        for (int j = 0; j < TN; j++) acc[i][j] = 0.f;

    int arow = tid >> 1;        // 0..127
    int acol = (tid & 1) * 4;   // 0 or 4
    int brow = tid >> 5;        // 0..7
    int bcol = (tid & 31) * 4;  // 0..124

    int tm0 = (tid >> 4) * TM;
    int tn0 = (tid & 15) * TN;

    const float* Aptr = &A[(long)(bm + arow) * lda + acol];
    const float* Bptr = TRANSB ? &Bm[(long)(bn + arow) * ldb + acol]
                               : &Bm[(long)brow * ldb + bn + bcol];

    // prologue: load tile 0 into buffer 0
    {
        float4 av = *(const float4*)Aptr;
        As[0][acol + 0][arow] = av.x;
        As[0][acol + 1][arow] = av.y;
        As[0][acol + 2][arow] = av.z;
        As[0][acol + 3][arow] = av.w;
        if (!TRANSB) {
            *(float4*)&Bs[0][brow][bcol] = *(const float4*)Bptr;
        } else {
            float4 bv = *(const float4*)Bptr;
            Bs[0][acol + 0][arow] = bv.x;
            Bs[0][acol + 1][arow] = bv.y;
            Bs[0][acol + 2][arow] = bv.z;
            Bs[0][acol + 3][arow] = bv.w;
        }
    }
    __syncthreads();

    int nIter = K / BK;
    for (int it = 0; it < nIter; it++) {
        int cur = it & 1, nxt = cur ^ 1;

        // issue next-tile global loads early (overlap with compute)
        float4 av, bv;
        bool have_next = (it + 1 < nIter);
        if (have_next) {
            int k0n = (it + 1) * BK;
            av = *(const float4*)(Aptr + k0n);
            bv = TRANSB ? *(const float4*)(Bptr + k0n)
                        : *(const float4*)(Bptr + (long)k0n * ldb);
        }

        // compute on current buffer
        #pragma unroll
        for (int k = 0; k < BK; k++) {
            float4 a0 = *(const float4*)&As[cur][k][tm0];
            float4 a1 = *(const float4*)&As[cur][k][tm0 + 4];
            float4 b0 = *(const float4*)&Bs[cur][k][tn0];
            float4 b1 = *(const float4*)&Bs[cur][k][tn0 + 4];
            float ra[8] = {a0.x, a0.y, a0.z, a0.w, a1.x, a1.y, a1.z, a1.w};
            float rb[8] = {b0.x, b0.y, b0.z, b0.w, b1.x, b1.y, b1.z, b1.w};
            #pragma unroll
            for (int i = 0; i < TM; i++)
                #pragma unroll
                for (int j = 0; j < TN; j++)
                    acc[i][j] += ra[i] * rb[j];
        }

        // stage next tile into the other buffer
        if (have_next) {
            As[nxt][acol + 0][arow] = av.x;
            As[nxt][acol + 1][arow] = av.y;
            As[nxt][acol + 2][arow] = av.z;
            As[nxt][acol + 3][arow] = av.w;
            if (!TRANSB) {
                *(float4*)&Bs[nxt][brow][bcol] = bv;
            } else {
                Bs[nxt][acol + 0][arow] = bv.x;
                Bs[nxt][acol + 1][arow] = bv.y;
                Bs[nxt][acol + 2][arow] = bv.z;
                Bs[nxt][acol + 3][arow] = bv.w;
            }
            __syncthreads();
        }
    }

    #pragma unroll
    for (int i = 0; i < TM; i++) {
        long m = bm + tm0 + i;
        #pragma unroll
        for (int j = 0; j < TN; j++) {
            int n = bn + tn0 + j;
            float v = acc[i][j];
            if (EPI == 1 || EPI == 2 || EPI == 4) v += bias[n];
            if (EPI == 2) v = 0.5f * v * (1.0f + erff(v * 0.70710678118654752f));
            long idx = m * (long)ldc + n;
            if (EPI == 3 || EPI == 4) C[idx] += v;
            else C[idx] = v;
        }
    }
}

// ---------------- LayerNorm -------------------------------------------------
__global__ __launch_bounds__(256) void ln_k(const float* __restrict__ x,
                                            const float* __restrict__ g,
                                            const float* __restrict__ b,
                                            float* __restrict__ y)
{
    long row = blockIdx.x;
    int t = threadIdx.x;
    float4 v = ((const float4*)(x + row * D_))[t];
    float s = v.x + v.y + v.z + v.w;
    float mu = blockReduceSum(s) * (1.f / D_);
    float dx0 = v.x - mu, dx1 = v.y - mu, dx2 = v.z - mu, dx3 = v.w - mu;
    float s2 = dx0 * dx0 + dx1 * dx1 + dx2 * dx2 + dx3 * dx3;
    float var = blockReduceSum(s2) * (1.f / D_);
    float inv = 1.0f / sqrtf(var + 1e-5f);
    float4 gg = ((const float4*)g)[t];
    float4 bb = ((const float4*)b)[t];
    float4 o;
    o.x = dx0 * inv * gg.x + bb.x;
    o.y = dx1 * inv * gg.y + bb.y;
    o.z = dx2 * inv * gg.z + bb.z;
    o.w = dx3 * inv * gg.w + bb.w;
    ((float4*)(y + row * D_))[t] = o;
}

// ---------------- RoPE ------------------------------------------------------
__global__ void rope_precompute_k(const int* __restrict__ positions,
                                  float* __restrict__ cosT, float* __restrict__ sinT)
{
    long idx = (long)blockIdx.x * blockDim.x + threadIdx.x;
    if (idx >= (long)ROWS_ * HD2_) return;
    long row = idx / HD2_;
    int i = (int)(idx % HD2_);
    double invf = pow(10000.0, -(double)i / 128.0);
    float angf = (float)positions[row] * (float)invf;  // fp32 product like reference
    double ang = (double)angf;
    cosT[idx] = (float)cos(ang);
    sinT[idx] = (float)sin(ang);
}

__global__ void rope_apply_k(float* __restrict__ qkv,
                             const float* __restrict__ cosT,
                             const float* __restrict__ sinT)
{
    long idx = (long)blockIdx.x * blockDim.x + threadIdx.x; // ROWS_ * 2 * H_ * HD2_
    long row = idx >> 10;       // / 1024
    int r = (int)(idx & 1023);
    int which = r >> 9;         // 0=q, 1=k
    int hh = (r >> 7) & 3;      // head
    int i = r & 127;
    long base = row * (3 * D_) + (long)which * D_ + (long)hh * HD_;
    float x1 = qkv[base + i];
    float x2 = qkv[base + i + HD2_];
    float c = cosT[row * HD2_ + i];
    float s = sinT[row * HD2_ + i];
    qkv[base + i]        = x1 * c - x2 * s;
    qkv[base + i + HD2_] = x1 * s + x2 * c;
}

// ---------------- Softmax (with mask + scale) -------------------------------
__global__ __launch_bounds__(256) void softmax_k(float* __restrict__ scores,
                                                 const float* __restrict__ mask)
{
    long row = blockIdx.x;            // (b*H + h)*M + i
    int b = (int)(row / ((long)H_ * M_));
    float* sr = scores + row * M_;
    const float* mr = mask + (long)b * M_;
    int t = threadIdx.x;
    float v[8];
    float mx = -INFINITY;
    #pragma unroll
    for (int c = 0; c < 8; c++) {
        int j = t + c * 256;
        float x = sr[j] * SCALE_;
        if (mr[j] == 0.f) x = -INFINITY;
        v[c] = x;
        mx = fmaxf(mx, x);
    }
    mx = blockReduceMax(mx);
    float sum = 0.f;
    #pragma unroll
    for (int c = 0; c < 8; c++) {
        v[c] = expf(v[c] - mx);
        sum += v[c];
    }
    sum = blockReduceSum(sum);
    float inv = 1.f / sum;
    #pragma unroll
    for (int c = 0; c < 8; c++) sr[t + c * 256] = v[c] * inv;
}

// ---------------- final gather ---------------------------------------------
__global__ __launch_bounds__(256) void gather_k(const float* __restrict__ h,
                                                const float* __restrict__ mask,
                                                const float* __restrict__ start_state,
                                                float* __restrict__ out)
{
    int b = blockIdx.x;
    int t = threadIdx.x;
    float s = 0.f;
    for (int j = t; j < M_; j += 256) s += mask[(long)b * M_ + j];
    float len = blockReduceSum(s);
    int idx = (int)len - 1;
    if (idx < 0) idx = 0;
    const float* src = (len > 0.f) ? (h + ((long)b * M_ + idx) * D_) : start_state;
    for (int d = t; d < D_; d += 256) out[(long)b * D_ + d] = src[d];
}

// ---------------- orchestration --------------------------------------------
extern "C" void kernel_launch(void* const* d_in, const int* in_sizes, int n_in,
                              void* d_out, int out_size)
{
    const float* x          = (const float*)d_in[0];
    const int*   positions  = (const int*)  d_in[1];
    const float* mask       = (const float*)d_in[2];
    const float* in_w       = (const float*)d_in[3];
    const float* in_b       = (const float*)d_in[4];
    const float* qkv_w      = (const float*)d_in[5];
    const float* o_w        = (const float*)d_in[6];
    const float* ln1_g      = (const float*)d_in[7];
    const float* ln1_b      = (const float*)d_in[8];
    const float* ffn_w1     = (const float*)d_in[9];
    const float* ffn_b1     = (const float*)d_in[10];
    const float* ffn_w2     = (const float*)d_in[11];
    const float* ffn_b2     = (const float*)d_in[12];
    const float* ln2_g      = (const float*)d_in[13];
    const float* ln2_b      = (const float*)d_in[14];
    const float* start_state= (const float*)d_in[15];
    float* out = (float*)d_out;

    float *h, *y, *qkv, *scores, *attn, *ffn, *cosT, *sinT;
    cudaGetSymbolAddress((void**)&h, g_h);
    cudaGetSymbolAddress((void**)&y, g_y);
    cudaGetSymbolAddress((void**)&qkv, g_qkv);
    cudaGetSymbolAddress((void**)&scores, g_scores);
    cudaGetSymbolAddress((void**)&attn, g_attn);
    cudaGetSymbolAddress((void**)&ffn, g_ffn);
    cudaGetSymbolAddress((void**)&cosT, g_cos);
    cudaGetSymbolAddress((void**)&sinT, g_sin);

    // in-proj: h = x @ in_w + in_b   [8192,512]@[512,1024]
    gemm_k<1, 0><<<dim3(D_ / BN, ROWS_ / BM, 1), 256>>>(
        x, in_w, in_b, h, IN_DIM_, IN_DIM_, D_, D_, 1, 0, 0, 0, 0, 0, 0);

    // rope tables
    {
        long n = (long)ROWS_ * HD2_;
        rope_precompute_k<<<(unsigned)((n + 255) / 256), 256>>>(positions, cosT, sinT);
    }

    for (int l = 0; l < NL_; l++) {
        const float* qw  = qkv_w  + (long)l * D_ * 3 * D_;
        const float* ow  = o_w    + (long)l * D_ * D_;
        const float* w1  = ffn_w1 + (long)l * D_ * FF_;
        const float* b1  = ffn_b1 + (long)l * FF_;
        const float* w2  = ffn_w2 + (long)l * FF_ * D_;
        const float* b2  = ffn_b2 + (long)l * D_;

        // LN1
        ln_k<<<ROWS_, 256>>>(h, ln1_g + l * D_, ln1_b + l * D_, y);

        // qkv = y @ qkv_w[l]   [8192,1024]@[1024,3072]
        gemm_k<0, 0><<<dim3(3 * D_ / BN, ROWS_ / BM, 1), 256>>>(
            y, qw, nullptr, qkv, D_, D_, 3 * D_, 3 * D_, 1, 0, 0, 0, 0, 0, 0);

        // rope on q,k
        rope_apply_k<<<(ROWS_ * 1024) / 256, 256>>>(qkv, cosT, sinT);

        // scores = Q @ K^T  per (b,h): [2048,256]@[256,2048]
        gemm_k<0, 1><<<dim3(M_ / BN, M_ / BM, B_ * H_), 256>>>(
            qkv /*Q*/, qkv + D_ /*K*/, nullptr, scores,
            HD_, 3 * D_, 3 * D_, M_, H_,
            (long)M_ * 3 * D_, HD_,            // A strides (b, h)
            (long)M_ * 3 * D_, HD_,            // B strides
            (long)H_ * M_ * M_, (long)M_ * M_);// C strides

        // softmax rows
        softmax_k<<<B_ * H_ * M_, 256>>>(scores, mask);

        // attn = P @ V  per (b,h): [2048,2048]@[2048,256]
        gemm_k<0, 0><<<dim3(HD_ / BN, M_ / BM, B_ * H_), 256>>>(
            scores, qkv + 2 * D_ /*V*/, nullptr, attn,
            M_, M_, 3 * D_, D_, H_,
            (long)H_ * M_ * M_, (long)M_ * M_,
            (long)M_ * 3 * D_, HD_,
            (long)M_ * D_, HD_);

        // h += attn @ o_w[l]
        gemm_k<3, 0><<<dim3(D_ / BN, ROWS_ / BM, 1), 256>>>(
            attn, ow, nullptr, h, D_, D_, D_, D_, 1, 0, 0, 0, 0, 0, 0);

        // LN2
        ln_k<<<ROWS_, 256>>>(h, ln2_g + l * D_, ln2_b + l * D_, y);

        // ffn hidden = gelu(y @ w1 + b1)
        gemm_k<2, 0><<<dim3(FF_ / BN, ROWS_ / BM, 1), 256>>>(
            y, w1, b1, ffn, D_, D_, FF_, FF_, 1, 0, 0, 0, 0, 0, 0);

        // h += ffn @ w2 + b2
        gemm_k<4, 0><<<dim3(D_ / BN, ROWS_ / BM, 1), 256>>>(
            ffn, w2, b2, h, FF_, FF_, D_, D_, 1, 0, 0, 0, 0, 0, 0);
    }

    // gather last valid token (or start_state)
    gather_k<<<B_, 256>>>(h, mask, start_state, out);
}